// round 3
// baseline (speedup 1.0000x reference)
#include <cuda_runtime.h>

#define Hh 64
#define Ww 64
#define CIN 512
#define OCN 128
#define NPIX 4096
#define CHUNK 2

typedef unsigned long long ull;

// Scratch (no allocations allowed)
__device__ float g_Wt[2 * CIN * 9 * OCN];   // [conv][ic][tap][oc]
__device__ float g_sums[2 * 2 * OCN];       // [conv][b][oc]
__device__ float g_cc[2 * 512];             // [b][ch]

__device__ __forceinline__ void fma2(ull& acc, ull a, ull b) {
    asm("fma.rn.f32x2 %0, %1, %2, %0;" : "+l"(acc) : "l"(a), "l"(b));
}

// ---------------------------------------------------------------------------
// Kernel 1: transpose weights to [conv][ic][tap][oc]; zero the sum scratch.
// ---------------------------------------------------------------------------
__global__ void prep_kernel(const float* __restrict__ W2, const float* __restrict__ W4) {
    int idx = blockIdx.x * blockDim.x + threadIdx.x;
    if (idx < 2 * 2 * OCN) g_sums[idx] = 0.f;
    const int PER = OCN * CIN * 9;  // 589824
    if (idx < 2 * PER) {
        int conv = idx / PER;
        int r = idx - conv * PER;            // = oc*4608 + ic*9 + tap
        int oc = r / (CIN * 9);
        int s = r - oc * (CIN * 9);
        int ic = s / 9;
        int tap = s - ic * 9;
        const float* Wsrc = conv ? W4 : W2;
        g_Wt[conv * PER + (ic * 9 + tap) * OCN + oc] = Wsrc[r];
    }
}

// ---------------------------------------------------------------------------
// Kernel 2: dilated conv (512->128) + bias + relu + spatial-sum.
// One block per (row, conv, batch). 256 threads.
// Warp layout: warpRow (oc half) x pxw (16-px chunk); lane = 8 oc-groups x 4 px-groups.
// Per thread: 8 oc x 4 px, accumulators as (oc, px-pair) f32x2.
// Weights in smem as duplicated pairs (w,w), groups of 8 ull padded to 10
// (80B stride -> conflict-free LDS.128). x in two parity-shifted copies so
// every tap's float2 load is 8B-aligned (dilation is odd).
// ---------------------------------------------------------------------------
__global__ void __launch_bounds__(256, 2)
conv_reduce_kernel(const float* __restrict__ x, const float* __restrict__ b2,
                   const float* __restrict__ b4) {
    __shared__ ull   sWdup[CHUNK][9][160];   // [ic][tap][group*10 + slot]
    __shared__ float sXe[CHUNK][3][80];      // base 8 (even offsets: center tap)
    __shared__ float sXo[CHUNK][3][80];      // base 7 (odd offsets: +-d taps)
    __shared__ float sRed[OCN];

    int row  = blockIdx.x;
    int conv = blockIdx.y;   // 0: W2,d=3   1: W4,d=7
    int bb   = blockIdx.z;
    int d = conv ? 7 : 3;
    const float* bias = conv ? b4 : b2;
    const float* xb = x + bb * CIN * NPIX;
    const float* Wt = g_Wt + conv * (OCN * CIN * 9);

    int tid  = threadIdx.x;
    int warp = tid >> 5;
    int lane = tid & 31;
    int warpRow = warp >> 2;          // 0..1 : oc half
    int pxw     = warp & 3;           // 0..3 : 16-px chunk
    int ocg     = lane & 7;           // 0..7
    int pxg     = lane >> 3;          // 0..3
    int G   = warpRow * 8 + ocg;      // weight group 0..15 (oc = 8G..8G+7)
    int px0 = pxw * 16 + pxg * 4;     // this thread's 4 px

    // zero x pads (edges never rewritten -> stay zero) and reduction buffer
    for (int i = tid; i < CHUNK * 3 * 80; i += 256) {
        ((float*)sXe)[i] = 0.f;
        ((float*)sXo)[i] = 0.f;
    }
    if (tid < OCN) sRed[tid] = 0.f;

    ull acc[8][2];
#pragma unroll
    for (int s = 0; s < 8; ++s) { acc[s][0] = 0ull; acc[s][1] = 0ull; }

#pragma unroll 1
    for (int ic0 = 0; ic0 < CIN; ic0 += CHUNK) {
        __syncthreads();
        // ---- weight fill: read float2, store duplicated float4 {w0,w0,w1,w1}
        {
            const float2* wsrc = (const float2*)(Wt + ic0 * 9 * OCN);
            float4* wdst = (float4*)&sWdup[0][0][0];
#pragma unroll
            for (int t = 0; t < 5; ++t) {
                int i = tid + t * 256;            // 0..1151 float2s
                if (i < CHUNK * 9 * 64) {
                    float2 wv = wsrc[i];
                    int ictap = i >> 6;           // /64
                    int oc = (i & 63) << 1;
                    int g = oc >> 3, s = oc & 7;  // s even
                    float4 dv;
                    dv.x = wv.x; dv.y = wv.x; dv.z = wv.y; dv.w = wv.y;
                    wdst[(ictap * 160 + g * 10 + s) >> 1] = dv;
                }
            }
        }
        // ---- x fill: CHUNK ic x 3 rows x 64 cols into both parity copies
#pragma unroll
        for (int t = 0; t < 2; ++t) {
            int i = tid + t * 256;                // 0..383
            if (i < CHUNK * 3 * 64) {
                int ic_l = i / 192;
                int rem = i - ic_l * 192;
                int r = rem >> 6;
                int col = rem & 63;
                int yy = row + (r - 1) * d;
                float v = 0.f;
                if (yy >= 0 && yy < Hh) v = xb[(ic0 + ic_l) * NPIX + yy * Ww + col];
                sXe[ic_l][r][8 + col] = v;
                sXo[ic_l][r][7 + col] = v;
            }
        }
        __syncthreads();

#pragma unroll
        for (int ic_l = 0; ic_l < CHUNK; ++ic_l) {
#pragma unroll
            for (int r = 0; r < 3; ++r) {
                const float* xeP = &sXe[ic_l][r][8 + px0];
                const float* xoP = &sXo[ic_l][r][7 + px0];
#pragma unroll
                for (int c = 0; c < 3; ++c) {
                    const float* xp = (c == 1) ? xeP : (xoP + (c - 1) * d);
                    ull x0 = *(const ull*)(xp);
                    ull x1 = *(const ull*)(xp + 2);
                    const ull* wp = &sWdup[ic_l][r * 3 + c][G * 10];
                    ull w[8];
                    *(float4*)&w[0] = ((const float4*)wp)[0];
                    *(float4*)&w[2] = ((const float4*)wp)[1];
                    *(float4*)&w[4] = ((const float4*)wp)[2];
                    *(float4*)&w[6] = ((const float4*)wp)[3];
#pragma unroll
                    for (int s = 0; s < 8; ++s) {
                        fma2(acc[s][0], w[s], x0);
                        fma2(acc[s][1], w[s], x1);
                    }
                }
            }
        }
    }

    __syncthreads();
    // bias + relu + sum over 4 px, reduce over pxg lanes, then block, then global
#pragma unroll
    for (int s = 0; s < 8; ++s) {
        int oc = 8 * G + s;
        float b = bias[oc];
        float2 v0 = *(float2*)&acc[s][0];
        float2 v1 = *(float2*)&acc[s][1];
        float sum = fmaxf(v0.x + b, 0.f) + fmaxf(v0.y + b, 0.f) +
                    fmaxf(v1.x + b, 0.f) + fmaxf(v1.y + b, 0.f);
        sum += __shfl_xor_sync(0xffffffffu, sum, 8);
        sum += __shfl_xor_sync(0xffffffffu, sum, 16);
        if (pxg == 0) atomicAdd(&sRed[oc], sum);
    }
    __syncthreads();
    if (tid < OCN) atomicAdd(&g_sums[(conv * 2 + bb) * OCN + tid], sRed[tid]);
}

// ---------------------------------------------------------------------------
// Kernel 3: tiny GEMV chain (attention collapses through GAP; softmax rows sum
// to 1 so GAP(o) = Wd @ mean(a); ccifl's length-1 softmax == 1).
// ---------------------------------------------------------------------------
__global__ void head_kernel(const float* __restrict__ Wd, const float* __restrict__ Wcc,
                            const float* __restrict__ bcc, const float* __restrict__ Wd2) {
    __shared__ float m[2][2][OCN];
    __shared__ float g1[2][2][512];
    __shared__ float gs[2][512];
    __shared__ float zs[2][256];
    int tid = threadIdx.x;  // 512

    if (tid < 512) ((float*)m)[tid] = g_sums[tid] * (1.f / NPIX);
    __syncthreads();

    for (int i = tid; i < 2048; i += 512) {
        int conv = i >> 10;
        int b = (i >> 9) & 1;
        int o = i & 511;
        const float* w = Wd + o * OCN;
        const float* mm = m[conv][b];
        float s = 0.f;
#pragma unroll 8
        for (int c = 0; c < OCN; ++c) s += w[c] * mm[c];
        g1[conv][b][o] = s;
    }
    __syncthreads();
    for (int i = tid; i < 1024; i += 512) {
        int b = i >> 9;
        int o = i & 511;
        gs[b][o] = g1[0][b][o] + g1[1][b][o];
    }
    __syncthreads();
    if (tid < 512) {
        int b = tid >> 8;
        int o = tid & 255;
        const float* w = Wcc + o * 512;
        float s = 2.f * bcc[o];
#pragma unroll 8
        for (int c = 0; c < 512; ++c) s += w[c] * gs[b][c];
        zs[b][o] = s;
    }
    __syncthreads();
    for (int i = tid; i < 1024; i += 512) {
        int b = i >> 9;
        int o = i & 511;
        const float* w = Wd2 + o * 256;
        float s = 0.f;
#pragma unroll 8
        for (int c = 0; c < 256; ++c) s += w[c] * zs[b][c];
        g_cc[b * 512 + o] = s;
    }
}

// ---------------------------------------------------------------------------
// Kernel 4: out[b,ch,h,w] = x[b,ch,h,w] + cc[b,ch]   (vectorized float4)
// ---------------------------------------------------------------------------
__global__ void add_kernel(const float* __restrict__ x, float* __restrict__ out) {
    int idx = blockIdx.x * blockDim.x + threadIdx.x;
    const int TOT4 = 2 * 512 * NPIX / 4;
    if (idx < TOT4) {
        int row = idx >> 10;
        float c = g_cc[row];
        float4 v = ((const float4*)x)[idx];
        v.x += c; v.y += c; v.z += c; v.w += c;
        ((float4*)out)[idx] = v;
    }
}

extern "C" void kernel_launch(void* const* d_in, const int* in_sizes, int n_in,
                              void* d_out, int out_size) {
    const float* x   = (const float*)d_in[0];
    const float* W2  = (const float*)d_in[3];
    const float* b2  = (const float*)d_in[4];
    const float* W4  = (const float*)d_in[7];
    const float* b4  = (const float*)d_in[8];
    const float* Wd  = (const float*)d_in[9];
    const float* Wcc = (const float*)d_in[10];
    const float* bcc = (const float*)d_in[11];
    const float* Wd2 = (const float*)d_in[12];
    float* out = (float*)d_out;

    prep_kernel<<<(2 * OCN * CIN * 9 + 255) / 256, 256>>>(W2, W4);
    dim3 grid(Hh, 2, 2);
    conv_reduce_kernel<<<grid, 256>>>(x, b2, b4);
    head_kernel<<<1, 512>>>(Wd, Wcc, bcc, Wd2);
    add_kernel<<<(2 * 512 * NPIX / 4 + 255) / 256, 256>>>(x, out);
}

// round 10
// speedup vs baseline: 2.4837x; 2.4837x over previous
#include <cuda_runtime.h>
#include <cuda_bf16.h>

#define Hh 64
#define Ww 64
#define CIN 512
#define OCN 128
#define NPIX 4096
#define KC 16
#define NCHUNK (CIN / KC)   // 32

typedef unsigned int u32;

// Scratch (no allocations): weight fragments, bf16 x copy, reductions
__device__ u32 gWf[2 * NCHUNK * 9 * 8 * 32 * 4];       // [conv][chunk][tap][ocTile][lane][reg]
__device__ __nv_bfloat16 gXbf[2 * CIN * NPIX];          // bf16 copy of x
__device__ float g_sums[2 * 2 * OCN];                   // [conv][b][oc]
__device__ float g_cc[2 * 512];                         // [b][ch]

__device__ __forceinline__ void mma16816(float* c, const u32* a, u32 b0, u32 b1) {
    asm volatile(
        "mma.sync.aligned.m16n8k16.row.col.f32.bf16.bf16.f32 "
        "{%0,%1,%2,%3}, {%4,%5,%6,%7}, {%8,%9}, {%0,%1,%2,%3};"
        : "+f"(c[0]), "+f"(c[1]), "+f"(c[2]), "+f"(c[3])
        : "r"(a[0]), "r"(a[1]), "r"(a[2]), "r"(a[3]), "r"(b0), "r"(b1));
}

// ---------------------------------------------------------------------------
// Kernel 1: build mma A-fragments from W2/W4, convert x to bf16, zero sums.
// FRAG_N = 589824 u32 (all weights); X_N = 2097152 u32 (all of x as bf16x2).
// Grid must cover max(X_N, FRAG_N) -- this was the R7 bug (only FRAG_N covered,
// leaving 72% of gXbf zero).
// Fragment map (m16n8k16 A, row-major): lane r=lane>>2, tig=lane&3;
//   reg0=(r, k=2tig,2tig+1) reg1=(r+8, klo) reg2=(r, k+8) reg3=(r+8, k+8)
// ---------------------------------------------------------------------------
__global__ void prep_kernel(const float* __restrict__ x, const float* __restrict__ W2,
                            const float* __restrict__ W4) {
    int idx = blockIdx.x * blockDim.x + threadIdx.x;
    if (idx < 2 * 2 * OCN) g_sums[idx] = 0.f;

    const int FRAG_N = 2 * NCHUNK * 9 * 8 * 32 * 4;   // 589824
    if (idx < FRAG_N) {
        int t = idx;
        int reg = t & 3;  t >>= 2;
        int lane = t & 31; t >>= 5;
        int ocTile = t & 7; t >>= 3;
        int tap = t % 9;  t /= 9;
        int chunk = t & 31; t >>= 5;
        int conv = t;
        int r = lane >> 2, tig = lane & 3;
        int oc = ocTile * 16 + r + ((reg & 1) ? 8 : 0);
        int ic = chunk * KC + 2 * tig + ((reg & 2) ? 8 : 0);
        const float* W = conv ? W4 : W2;
        float w0 = W[oc * (CIN * 9) + ic * 9 + tap];
        float w1 = W[oc * (CIN * 9) + (ic + 1) * 9 + tap];
        __nv_bfloat162 p = __floats2bfloat162_rn(w0, w1);   // .x (=w0) in low 16
        gWf[idx] = *(u32*)&p;
    }
    if (idx < 2 * CIN * NPIX / 2) {
        float2 v = ((const float2*)x)[idx];
        __nv_bfloat162 p = __floats2bfloat162_rn(v.x, v.y);
        ((u32*)gXbf)[idx] = *(u32*)&p;
    }
}

// ---------------------------------------------------------------------------
// Kernel 2: implicit-GEMM dilated conv on tensor cores + bias + relu + mean.
// Block = (row, conv, batch): C tile 128 oc x 64 px. 8 warps:
//   warpM = warp>>1 (32 oc), warpN = warp&1 (32 px); per warp 2 m-tiles x 4 n-tiles.
// K-loop: 32 chunks of 16 ic; per chunk 9 taps (dilation = column/row shifts).
// A staged in fragment order (pure LDG.128->STS.128). B stored [row][col+8][icpair]
// so every frag load is an LDS.32; pads are zeroed once and never rewritten.
// ---------------------------------------------------------------------------
__global__ void __launch_bounds__(256, 2)
conv_mma_kernel(const float* __restrict__ b2, const float* __restrict__ b4) {
    __shared__ u32 sWA[9 * 8 * 32 * 4];    // 9216 u32 = 36 KB
    __shared__ u32 sXB[3 * 80 * 10];       // [r][col(8+64+8)][icpair(8,pad10)] = 9.6 KB
    __shared__ float sRed[OCN];

    int row  = blockIdx.x;
    int conv = blockIdx.y;        // 0: W2,d=3   1: W4,d=7
    int bb   = blockIdx.z;
    int d = conv ? 7 : 3;

    int tid = threadIdx.x;
    int warp = tid >> 5;
    int lane = tid & 31;
    int warpM = warp >> 1;        // 0..3
    int warpN = warp & 1;         // 0..1

    for (int i = tid; i < 3 * 80 * 10; i += 256) sXB[i] = 0;
    if (tid < OCN) sRed[tid] = 0.f;

    int yy[3]; bool yv[3];
#pragma unroll
    for (int r = 0; r < 3; ++r) {
        yy[r] = row + (r - 1) * d;
        yv[r] = (yy[r] >= 0) && (yy[r] < Hh);
    }

    const __nv_bfloat16* xb = gXbf + bb * CIN * NPIX;
    const u32* wsrc = gWf + conv * (NCHUNK * 9216);

    float acc[2][4][4];
#pragma unroll
    for (int mt = 0; mt < 2; ++mt)
#pragma unroll
        for (int nt = 0; nt < 4; ++nt)
#pragma unroll
            for (int k = 0; k < 4; ++k) acc[mt][nt][k] = 0.f;

#pragma unroll 1
    for (int chunk = 0; chunk < NCHUNK; ++chunk) {
        __syncthreads();
        // A fill: 36 KB contiguous, 9 x LDG.128 per thread
        {
            const float4* asrc = (const float4*)(wsrc + chunk * 9216);
            float4* adst = (float4*)sWA;
#pragma unroll
            for (int t = 0; t < 9; ++t) adst[tid + t * 256] = asrc[tid + t * 256];
        }
        // B fill: 3 rows x 64 cols x 8 icpairs (lane over col -> coalesced 2B loads)
#pragma unroll
        for (int t = 0; t < 6; ++t) {
            int i = tid + t * 256;
            int col = i & 63;
            int rest = i >> 6;              // r*8 + icp
            int r = rest >> 3, icp = rest & 7;
            u32 val = 0;
            if (yv[r]) {
                const __nv_bfloat16* p = xb + (chunk * KC + icp * 2) * NPIX + yy[r] * Ww + col;
                unsigned short lo = *(const unsigned short*)p;
                unsigned short hi = *(const unsigned short*)(p + NPIX);
                val = (u32)lo | ((u32)hi << 16);
            }
            sXB[(r * 80 + col + 8) * 10 + icp] = val;
        }
        __syncthreads();

#pragma unroll
        for (int r = 0; r < 3; ++r) {
#pragma unroll
            for (int c = 0; c < 3; ++c) {
                int tap = r * 3 + c;
                u32 a[2][4];
#pragma unroll
                for (int mt = 0; mt < 2; ++mt) {
                    int ocTile = warpM * 2 + mt;
                    *(float4*)a[mt] =
                        *(const float4*)&sWA[((tap * 8 + ocTile) * 32 + lane) * 4];
                }
                int scBase = r * 80 + (c - 1) * d + 8 + (lane >> 2);
                int tig = lane & 3;
#pragma unroll
                for (int nt = 0; nt < 4; ++nt) {
                    int px = warpN * 32 + nt * 8;
                    int bidx = (scBase + px) * 10 + tig;
                    u32 b0 = sXB[bidx];
                    u32 b1 = sXB[bidx + 4];
                    mma16816(acc[0][nt], a[0], b0, b1);
                    mma16816(acc[1][nt], a[1], b0, b1);
                }
            }
        }
    }

    __syncthreads();
    const float* bias = conv ? b4 : b2;
#pragma unroll
    for (int mt = 0; mt < 2; ++mt) {
        int oc0 = warpM * 32 + mt * 16 + (lane >> 2);
        float bA = bias[oc0], bB = bias[oc0 + 8];
        float sA = 0.f, sB = 0.f;
#pragma unroll
        for (int nt = 0; nt < 4; ++nt) {
            sA += fmaxf(acc[mt][nt][0] + bA, 0.f) + fmaxf(acc[mt][nt][1] + bA, 0.f);
            sB += fmaxf(acc[mt][nt][2] + bB, 0.f) + fmaxf(acc[mt][nt][3] + bB, 0.f);
        }
        sA += __shfl_xor_sync(0xffffffffu, sA, 1);
        sA += __shfl_xor_sync(0xffffffffu, sA, 2);
        sB += __shfl_xor_sync(0xffffffffu, sB, 1);
        sB += __shfl_xor_sync(0xffffffffu, sB, 2);
        if ((lane & 3) == 0) {
            atomicAdd(&sRed[oc0], sA);
            atomicAdd(&sRed[oc0 + 8], sB);
        }
    }
    __syncthreads();
    if (tid < OCN) atomicAdd(&g_sums[(conv * 2 + bb) * OCN + tid], sRed[tid]);
}

// ---------------------------------------------------------------------------
// Kernel 3: tiny GEMV chain (attention collapses through GAP; softmax rows sum
// to 1 so GAP(o) = Wd @ mean(a); ccifl's length-1 softmax == 1).
// ---------------------------------------------------------------------------
__global__ void head_kernel(const float* __restrict__ Wd, const float* __restrict__ Wcc,
                            const float* __restrict__ bcc, const float* __restrict__ Wd2) {
    __shared__ float m[2][2][OCN];
    __shared__ float g1[2][2][512];
    __shared__ float gs[2][512];
    __shared__ float zs[2][256];
    int tid = threadIdx.x;  // 512

    if (tid < 512) ((float*)m)[tid] = g_sums[tid] * (1.f / NPIX);
    __syncthreads();

    for (int i = tid; i < 2048; i += 512) {
        int conv = i >> 10;
        int b = (i >> 9) & 1;
        int o = i & 511;
        const float* w = Wd + o * OCN;
        const float* mm = m[conv][b];
        float s = 0.f;
#pragma unroll 8
        for (int c = 0; c < OCN; ++c) s += w[c] * mm[c];
        g1[conv][b][o] = s;
    }
    __syncthreads();
    for (int i = tid; i < 1024; i += 512) {
        int b = i >> 9;
        int o = i & 511;
        gs[b][o] = g1[0][b][o] + g1[1][b][o];
    }
    __syncthreads();
    if (tid < 512) {
        int b = tid >> 8;
        int o = tid & 255;
        const float* w = Wcc + o * 512;
        float s = 2.f * bcc[o];
#pragma unroll 8
        for (int c = 0; c < 512; ++c) s += w[c] * gs[b][c];
        zs[b][o] = s;
    }
    __syncthreads();
    for (int i = tid; i < 1024; i += 512) {
        int b = i >> 9;
        int o = i & 511;
        const float* w = Wd2 + o * 256;
        float s = 0.f;
#pragma unroll 8
        for (int c = 0; c < 256; ++c) s += w[c] * zs[b][c];
        g_cc[b * 512 + o] = s;
    }
}

// ---------------------------------------------------------------------------
// Kernel 4: out[b,ch,h,w] = x[b,ch,h,w] + cc[b,ch]   (vectorized float4)
// ---------------------------------------------------------------------------
__global__ void add_kernel(const float* __restrict__ x, float* __restrict__ out) {
    int idx = blockIdx.x * blockDim.x + threadIdx.x;
    const int TOT4 = 2 * 512 * NPIX / 4;
    if (idx < TOT4) {
        int row = idx >> 10;
        float c = g_cc[row];
        float4 v = ((const float4*)x)[idx];
        v.x += c; v.y += c; v.z += c; v.w += c;
        ((float4*)out)[idx] = v;
    }
}

extern "C" void kernel_launch(void* const* d_in, const int* in_sizes, int n_in,
                              void* d_out, int out_size) {
    const float* x   = (const float*)d_in[0];
    const float* W2  = (const float*)d_in[3];
    const float* b2  = (const float*)d_in[4];
    const float* W4  = (const float*)d_in[7];
    const float* b4  = (const float*)d_in[8];
    const float* Wd  = (const float*)d_in[9];
    const float* Wcc = (const float*)d_in[10];
    const float* bcc = (const float*)d_in[11];
    const float* Wd2 = (const float*)d_in[12];
    float* out = (float*)d_out;

    // Cover BOTH the weight-fragment range (589824) and the x-conversion
    // range (2*CIN*NPIX/2 = 2097152). R7 bug: only the former was covered.
    const int PREP_N = 2 * CIN * NPIX / 2;   // 2097152 (largest range)
    prep_kernel<<<(PREP_N + 255) / 256, 256>>>(x, W2, W4);
    dim3 grid(Hh, 2, 2);
    conv_mma_kernel<<<grid, 256>>>(b2, b4);
    head_kernel<<<1, 512>>>(Wd, Wcc, bcc, Wd2);
    add_kernel<<<(2 * 512 * NPIX / 4 + 255) / 256, 256>>>(x, out);
}